// round 14
// baseline (speedup 1.0000x reference)
#include <cuda_runtime.h>
#include <cuda_bf16.h>
#include <cstdint>

// ======================= problem constants =======================
// B=4096, D=512, rows = 2B = 8192. sim = F F^T / 0.1. Fixed shift C = 10.
// Symmetry: 2080 128x128 tiles, balanced over 148 CTAs. FP8 e4m3 (x16
// scale), sim = D/256. Epilogue of tile t-1 interleaved into tile t's
// MMA stream (dual accumulator bank) to keep the tensor pipe hot.
#define NROWS 8192
#define NDIM  512
#define NB    4096
#define EX2_A 0.05635527503f
#define EX2_B -14.4269504089f
#define NTILES_TOTAL 2080
#define NCTA 148
#define NTHREADS 512

// ======================= device scratch (no allocs allowed) =====
static __device__ __align__(16) uint8_t g_F8[NROWS * NDIM];  // 4 MB e4m3
static __device__ float g_pos[NB];
static __device__ float g_rowsum[NROWS];

// ======================= PTX helpers (non-'a' features only) =====
__device__ __forceinline__ uint32_t smem_u32(const void* p) {
    uint32_t a;
    asm("{ .reg .u64 t; cvta.to.shared.u64 t, %1; cvt.u32.u64 %0, t; }" : "=r"(a) : "l"(p));
    return a;
}
__device__ __forceinline__ void cp16(uint32_t saddr, const void* g) {
    asm volatile("cp.async.cg.shared.global [%0], [%1], 16;" :: "r"(saddr), "l"(g));
}
__device__ __forceinline__ void cp_commit() { asm volatile("cp.async.commit_group;" ::: "memory"); }
template <int N>
__device__ __forceinline__ void cp_wait() { asm volatile("cp.async.wait_group %0;" :: "n"(N) : "memory"); }

__device__ __forceinline__ void ldsm_x4(uint32_t& r0, uint32_t& r1, uint32_t& r2, uint32_t& r3,
                                        uint32_t addr) {
    asm volatile("ldmatrix.sync.aligned.m8n8.x4.shared.b16 {%0,%1,%2,%3}, [%4];"
                 : "=r"(r0), "=r"(r1), "=r"(r2), "=r"(r3)
                 : "r"(addr));
}
__device__ __forceinline__ void mma16832(float* d, uint32_t a0, uint32_t a1, uint32_t a2,
                                         uint32_t a3, uint32_t b0, uint32_t b1) {
    asm volatile(
        "mma.sync.aligned.m16n8k32.row.col.f32.e4m3.e4m3.f32 "
        "{%0,%1,%2,%3}, {%4,%5,%6,%7}, {%8,%9}, {%0,%1,%2,%3};"
        : "+f"(d[0]), "+f"(d[1]), "+f"(d[2]), "+f"(d[3])
        : "r"(a0), "r"(a1), "r"(a2), "r"(a3), "r"(b0), "r"(b1));
}
__device__ __forceinline__ uint32_t pack_e4m3x4(float x0, float x1, float x2, float x3) {
    uint16_t lo, hi;
    asm("cvt.rn.satfinite.e4m3x2.f32 %0, %1, %2;" : "=h"(lo) : "f"(x1), "f"(x0));
    asm("cvt.rn.satfinite.e4m3x2.f32 %0, %1, %2;" : "=h"(hi) : "f"(x3), "f"(x2));
    return (uint32_t)lo | ((uint32_t)hi << 16);
}
__device__ __forceinline__ void decode_tile(int idx, int& i, int& t) {
    if (idx < 1056) { i = idx / 33; t = idx - 33 * i; }
    else { int r = idx - 1056; i = 32 + (r >> 5); t = r & 31; }
}

// ======= kernel A: fused normalize -> e4m3 + exact pos sims + zero ======
// One block per pair index i: handles row i (f1) and row i+NB (f2); one
// 16 MB read serves normalization AND the exact fp32 positive-pair dot.
__global__ void k_norm_pos(const float* __restrict__ f1, const float* __restrict__ f2,
                           float* __restrict__ out) {
    int i = blockIdx.x;   // 0..4095
    int tid = threadIdx.x;  // 128
    if (tid == 0) { g_rowsum[i] = 0.f; g_rowsum[i + NB] = 0.f; }
    if (i == 0 && tid == 1) out[0] = 0.f;
    float4 v1 = *reinterpret_cast<const float4*>(f1 + (size_t)i * NDIM + tid * 4);
    float4 v2 = *reinterpret_cast<const float4*>(f2 + (size_t)i * NDIM + tid * 4);
    float s11 = v1.x * v1.x + v1.y * v1.y + v1.z * v1.z + v1.w * v1.w;
    float s22 = v2.x * v2.x + v2.y * v2.y + v2.z * v2.z + v2.w * v2.w;
    float s12 = v1.x * v2.x + v1.y * v2.y + v1.z * v2.z + v1.w * v2.w;
#pragma unroll
    for (int o = 16; o > 0; o >>= 1) {
        s11 += __shfl_xor_sync(0xFFFFFFFFu, s11, o);
        s22 += __shfl_xor_sync(0xFFFFFFFFu, s22, o);
        s12 += __shfl_xor_sync(0xFFFFFFFFu, s12, o);
    }
    __shared__ float r11[4], r22[4], r12[4];
    if ((tid & 31) == 0) { r11[tid >> 5] = s11; r22[tid >> 5] = s22; r12[tid >> 5] = s12; }
    __syncthreads();
    float t11 = r11[0] + r11[1] + r11[2] + r11[3];
    float t22 = r22[0] + r22[1] + r22[2] + r22[3];
    float inv1 = 1.f / fmaxf(sqrtf(t11), 1e-12f);
    float inv2 = 1.f / fmaxf(sqrtf(t22), 1e-12f);
    float sc1 = 16.f * inv1, sc2 = 16.f * inv2;
    reinterpret_cast<uint32_t*>(g_F8)[(size_t)i * (NDIM / 4) + tid] =
        pack_e4m3x4(v1.x * sc1, v1.y * sc1, v1.z * sc1, v1.w * sc1);
    reinterpret_cast<uint32_t*>(g_F8)[(size_t)(i + NB) * (NDIM / 4) + tid] =
        pack_e4m3x4(v2.x * sc2, v2.y * sc2, v2.z * sc2, v2.w * sc2);
    if (tid == 0) {
        float t12 = r12[0] + r12[1] + r12[2] + r12[3];
        g_pos[i] = t12 * inv1 * inv2 * 10.f;
    }
}

// ======================= kernel C: symmetric fused GEMM + exp-sum
// FP8, 512 threads = 16 warps (4M x 4N), warp tile 32x32, 148 CTAs.
// SMEM: A 128x512 e4m3 pitch 512B swizzled (64 KB); B 3-ring of 128x256
// fp8-k chunks (96 KB). The epilogue of the PREVIOUS tile is processed
// 2 values per ks step inside the current tile's MMA loop (accP bank),
// so MUFU/FMA runs under the tensor shadow. Frags single-buffered.
static constexpr int A_PITCH_B = 512;
static constexpr int B_PITCH_B = 256;
static constexpr int A_BYTES = 128 * A_PITCH_B;
static constexpr int B_BUF_BYTES = 128 * B_PITCH_B;
static constexpr int SMEM_DYN = A_BYTES + 3 * B_BUF_BYTES;  // 163840

__device__ __forceinline__ uint32_t swz(uint32_t row, uint32_t byteoff) {
    return byteoff ^ ((row & 7) << 4);
}

__device__ __forceinline__ void issue_chunk(uint32_t B_base, int tid, int i, int t0, int c) {
    int t = t0 + (c >> 1);
    int n0 = ((i + t) & 63) * 128;
    int kc = c & 1;
    uint32_t buf = B_base + (uint32_t)(c % 3) * B_BUF_BYTES;
#pragma unroll
    for (int u = 0; u < 4; u++) {
        int x = tid + u * NTHREADS;
        uint32_t row = (uint32_t)x >> 4, g = (uint32_t)x & 15;
        cp16(buf + row * B_PITCH_B + swz(row, g * 16),
             &g_F8[(size_t)(n0 + (int)row) * NDIM + kc * 256 + (int)g * 16]);
    }
}

__global__ __launch_bounds__(NTHREADS, 1) void k_infonce() {
    extern __shared__ char dyn[];
    uint32_t A_base = smem_u32(dyn);
    uint32_t B_base = A_base + A_BYTES;
    __shared__ float srow[128];

    int tid = threadIdx.x;
    int wid = tid >> 5, lane = tid & 31;
    int warpm = wid >> 2, warpn = wid & 3;  // 4 x 4, warp tile 32x32
    int g = blockIdx.x;
    int s = (g * NTILES_TOTAL) / NCTA;
    int e = ((g + 1) * NTILES_TOTAL) / NCTA;

    int rowadd = ((lane >> 3) & 1) * 8 + (lane & 7);
    int kadd = (lane >> 4) * 16;
    uint32_t xorm = ((uint32_t)lane & 7) << 4;

    uint32_t aRow[2];
#pragma unroll
    for (int mf = 0; mf < 2; mf++)
        aRow[mf] = A_base + (uint32_t)(warpm * 32 + mf * 16 + rowadd) * A_PITCH_B;
    uint32_t bRowRel[2];
#pragma unroll
    for (int nf = 0; nf < 2; nf++)
        bRowRel[nf] = (uint32_t)(warpn * 32 + nf * 16 + rowadd) * B_PITCH_B;

    // epilogue column bases for lane<4 flush and gc masking
    int colLane2 = 2 * (lane & 3);

    float acc[2][4][4];   // current tile accumulators
    float accP[2][4][4];  // previous tile (pending epilogue)
    float colAcc[8];
    uint32_t af[2][4], bf[2][4];

    while (s < e) {
        int rowtile, t0;
        decode_tile(s, rowtile, t0);
        int Trow = (rowtile < 32) ? 33 : 32;
        int ntiles = min(e - s, Trow - t0);
        s += ntiles;
        int C = ntiles * 2;
        int m0 = rowtile * 128;
        int grBase = m0 + warpm * 32 + (lane >> 2);
        float accRow[4] = {0.f, 0.f, 0.f, 0.f};
        bool havePrev = false, prevDiag = false;
        int prevN0 = 0;
#pragma unroll
        for (int x = 0; x < 8; x++) colAcc[x] = 0.f;

        if (tid < 128) srow[tid] = 0.f;

        // A via cp.async (64 KB, swizzled, pitch 512)
#pragma unroll
        for (int u = 0; u < 8; u++) {
            int x = tid + u * NTHREADS;
            uint32_t row = (uint32_t)x >> 5, gg = (uint32_t)x & 31;
            cp16(A_base + row * A_PITCH_B + swz(row, gg * 16),
                 &g_F8[(size_t)(m0 + (int)row) * NDIM + (int)gg * 16]);
        }
        cp_commit();
        issue_chunk(B_base, tid, rowtile, t0, 0);
        cp_commit();
        issue_chunk(B_base, tid, rowtile, t0, 1);
        cp_commit();

        for (int ti = 0; ti < ntiles; ++ti) {
            int t = t0 + ti;
            int n0 = ((rowtile + t) & 63) * 128;
#pragma unroll
            for (int mf = 0; mf < 2; mf++)
#pragma unroll
                for (int q = 0; q < 4; q++)
#pragma unroll
                    for (int j = 0; j < 4; j++) acc[mf][q][j] = 0.f;

#pragma unroll
            for (int kc = 0; kc < 2; ++kc) {
                int c = ti * 2 + kc;
                cp_wait<1>();
                __syncthreads();
                if (c + 2 < C) issue_chunk(B_base, tid, rowtile, t0, c + 2);
                cp_commit();

                uint32_t bBuf = B_base + (uint32_t)(c % 3) * B_BUF_BYTES;
#pragma unroll
                for (int ks = 0; ks < 8; ++ks) {
                    uint32_t koffA = (uint32_t)(kc * 256 + ks * 32 + kadd) ^ xorm;
                    uint32_t koffB = (uint32_t)(ks * 32 + kadd) ^ xorm;
#pragma unroll
                    for (int mf = 0; mf < 2; mf++)
                        ldsm_x4(af[mf][0], af[mf][1], af[mf][2], af[mf][3],
                                aRow[mf] + koffA);
#pragma unroll
                    for (int nf = 0; nf < 2; nf++)
                        ldsm_x4(bf[nf][0], bf[nf][1], bf[nf][2], bf[nf][3],
                                bBuf + bRowRel[nf] + koffB);
#pragma unroll
                    for (int nf = 0; nf < 2; nf++) {
#pragma unroll
                        for (int mf = 0; mf < 2; mf++) {
                            mma16832(acc[mf][nf * 2 + 0], af[mf][0], af[mf][1],
                                     af[mf][2], af[mf][3], bf[nf][0], bf[nf][2]);
                            mma16832(acc[mf][nf * 2 + 1], af[mf][0], af[mf][1],
                                     af[mf][2], af[mf][3], bf[nf][1], bf[nf][3]);
                        }
                    }

                    // Interleaved epilogue: 2 values of the previous tile
                    // per ks step (32 over the 16 steps of this tile).
                    if (havePrev) {
#pragma unroll
                        for (int h = 0; h < 2; h++) {
                            const int idx = (kc * 8 + ks) * 2 + h;
                            const int mf = idx >> 4, q = (idx >> 2) & 3, j = idx & 3;
                            float arg = fmaf(accP[mf][q][j], EX2_A, EX2_B);
                            float ev;
                            asm("ex2.approx.ftz.f32 %0, %1;" : "=f"(ev) : "f"(arg));
                            int gc = prevN0 + warpn * 32 + (q >> 1) * 16 + (q & 1) * 8 +
                                     colLane2 + (j & 1);
                            int gr = grBase + mf * 16 + (j >> 1) * 8;
                            bool keep = !prevDiag || (gc != gr);
                            if (keep) accRow[mf * 2 + (j >> 1)] += ev;
                            if (!prevDiag) colAcc[q * 2 + (j & 1)] += ev;
                        }
                    }
                }
            }

            // Tile boundary: flush prev tile's column sums, rotate banks.
            if (havePrev && !prevDiag) {
#pragma unroll
                for (int x = 0; x < 8; x++) {
                    float v = colAcc[x];
                    v += __shfl_xor_sync(0xFFFFFFFFu, v, 4);
                    v += __shfl_xor_sync(0xFFFFFFFFu, v, 8);
                    v += __shfl_xor_sync(0xFFFFFFFFu, v, 16);
                    if (lane < 4) {
                        int q = x >> 1, jlo = x & 1;
                        int col = prevN0 + warpn * 32 + (q >> 1) * 16 + (q & 1) * 8 +
                                  2 * lane + jlo;
                        atomicAdd(&g_rowsum[col], v);
                    }
                }
            }
#pragma unroll
            for (int x = 0; x < 8; x++) colAcc[x] = 0.f;
#pragma unroll
            for (int mf = 0; mf < 2; mf++)
#pragma unroll
                for (int q = 0; q < 4; q++)
#pragma unroll
                    for (int j = 0; j < 4; j++) accP[mf][q][j] = acc[mf][q][j];
            prevN0 = n0;
            prevDiag = (t == 0);
            havePrev = true;
        }

        // Segment end: drain the last pending epilogue serially.
        if (havePrev) {
#pragma unroll
            for (int mf = 0; mf < 2; mf++) {
#pragma unroll
                for (int q = 0; q < 4; q++) {
#pragma unroll
                    for (int j = 0; j < 4; j++) {
                        float arg = fmaf(accP[mf][q][j], EX2_A, EX2_B);
                        float ev;
                        asm("ex2.approx.ftz.f32 %0, %1;" : "=f"(ev) : "f"(arg));
                        int gc = prevN0 + warpn * 32 + (q >> 1) * 16 + (q & 1) * 8 +
                                 colLane2 + (j & 1);
                        int gr = grBase + mf * 16 + (j >> 1) * 8;
                        bool keep = !prevDiag || (gc != gr);
                        if (keep) accRow[mf * 2 + (j >> 1)] += ev;
                        if (!prevDiag) colAcc[q * 2 + (j & 1)] += ev;
                    }
                }
            }
            if (!prevDiag) {
#pragma unroll
                for (int x = 0; x < 8; x++) {
                    float v = colAcc[x];
                    v += __shfl_xor_sync(0xFFFFFFFFu, v, 4);
                    v += __shfl_xor_sync(0xFFFFFFFFu, v, 8);
                    v += __shfl_xor_sync(0xFFFFFFFFu, v, 16);
                    if (lane < 4) {
                        int q = x >> 1, jlo = x & 1;
                        int col = prevN0 + warpn * 32 + (q >> 1) * 16 + (q & 1) * 8 +
                                  2 * lane + jlo;
                        atomicAdd(&g_rowsum[col], v);
                    }
                }
            }
        }

        // Row flush (doubles as the drain barrier before next A reload).
        __syncthreads();
#pragma unroll
        for (int x = 0; x < 4; x++) {
            float v = accRow[x];
            v += __shfl_xor_sync(0xFFFFFFFFu, v, 1);
            v += __shfl_xor_sync(0xFFFFFFFFu, v, 2);
            if ((lane & 3) == 0)
                atomicAdd(&srow[warpm * 32 + x * 8 + (lane >> 2)], v);
        }
        __syncthreads();
        if (tid < 128)
            atomicAdd(&g_rowsum[m0 + tid], srow[tid]);
    }
}

// ======================= kernel D: final reduction ===============
__global__ void k_finish(float* __restrict__ out) {
    int tid = threadIdx.x;  // 256, grid 32
    int r = blockIdx.x * 256 + tid;
    float acc = 10.f + __logf(g_rowsum[r]) - g_pos[r & (NB - 1)];
#pragma unroll
    for (int o = 16; o > 0; o >>= 1) acc += __shfl_xor_sync(0xFFFFFFFFu, acc, o);
    __shared__ float sred[8];
    if ((tid & 31) == 0) sred[tid >> 5] = acc;
    __syncthreads();
    if (tid == 0) {
        float ssum = 0.f;
#pragma unroll
        for (int i = 0; i < 8; i++) ssum += sred[i];
        atomicAdd(out, ssum * (1.f / (float)NROWS));
    }
}

// ======================= launch ==================================
extern "C" void kernel_launch(void* const* d_in, const int* in_sizes, int n_in,
                              void* d_out, int out_size) {
    const float* f1 = (const float*)d_in[0];
    const float* f2 = (const float*)d_in[1];
    float* out = (float*)d_out;

    cudaFuncSetAttribute(k_infonce, cudaFuncAttributeMaxDynamicSharedMemorySize, SMEM_DYN);

    k_norm_pos<<<NB, 128>>>(f1, f2, out);
    k_infonce<<<NCTA, NTHREADS, SMEM_DYN>>>();
    k_finish<<<32, 256>>>(out);
}

// round 16
// speedup vs baseline: 1.0657x; 1.0657x over previous
#include <cuda_runtime.h>
#include <cuda_bf16.h>
#include <cstdint>

// ======================= problem constants =======================
// B=4096, D=512, rows = 2B = 8192. sim = F F^T / 0.1. Fixed shift C = 10.
// Symmetry: 2080 128x128 tiles, balanced over 296 CTAs (2 CTAs/SM so the
// co-resident CTA fills barrier/epilogue lockstep bubbles — R14 lesson).
// FP8 e4m3 (x16 scale), sim = D/256.
#define NROWS 8192
#define NDIM  512
#define NB    4096
#define EX2_A 0.05635527503f
#define EX2_B -14.4269504089f
#define NTILES_TOTAL 2080
#define NCTA 296
#define NTHREADS 256

// ======================= device scratch (no allocs allowed) =====
static __device__ __align__(16) uint8_t g_F8[NROWS * NDIM];  // 4 MB e4m3
static __device__ float g_pos[NB];
static __device__ float g_rowsum[NROWS];

// ======================= PTX helpers (non-'a' features only) =====
__device__ __forceinline__ uint32_t smem_u32(const void* p) {
    uint32_t a;
    asm("{ .reg .u64 t; cvta.to.shared.u64 t, %1; cvt.u32.u64 %0, t; }" : "=r"(a) : "l"(p));
    return a;
}
__device__ __forceinline__ void cp16(uint32_t saddr, const void* g) {
    asm volatile("cp.async.cg.shared.global [%0], [%1], 16;" :: "r"(saddr), "l"(g));
}
__device__ __forceinline__ void cp_commit() { asm volatile("cp.async.commit_group;" ::: "memory"); }
template <int N>
__device__ __forceinline__ void cp_wait() { asm volatile("cp.async.wait_group %0;" :: "n"(N) : "memory"); }

__device__ __forceinline__ void ldsm_x4(uint32_t& r0, uint32_t& r1, uint32_t& r2, uint32_t& r3,
                                        uint32_t addr) {
    asm volatile("ldmatrix.sync.aligned.m8n8.x4.shared.b16 {%0,%1,%2,%3}, [%4];"
                 : "=r"(r0), "=r"(r1), "=r"(r2), "=r"(r3)
                 : "r"(addr));
}
__device__ __forceinline__ void mma16832(float* d, uint32_t a0, uint32_t a1, uint32_t a2,
                                         uint32_t a3, uint32_t b0, uint32_t b1) {
    asm volatile(
        "mma.sync.aligned.m16n8k32.row.col.f32.e4m3.e4m3.f32 "
        "{%0,%1,%2,%3}, {%4,%5,%6,%7}, {%8,%9}, {%0,%1,%2,%3};"
        : "+f"(d[0]), "+f"(d[1]), "+f"(d[2]), "+f"(d[3])
        : "r"(a0), "r"(a1), "r"(a2), "r"(a3), "r"(b0), "r"(b1));
}
__device__ __forceinline__ uint32_t pack_e4m3x4(float x0, float x1, float x2, float x3) {
    uint16_t lo, hi;
    asm("cvt.rn.satfinite.e4m3x2.f32 %0, %1, %2;" : "=h"(lo) : "f"(x1), "f"(x0));
    asm("cvt.rn.satfinite.e4m3x2.f32 %0, %1, %2;" : "=h"(hi) : "f"(x3), "f"(x2));
    return (uint32_t)lo | ((uint32_t)hi << 16);
}
__device__ __forceinline__ void decode_tile(int idx, int& i, int& t) {
    if (idx < 1056) { i = idx / 33; t = idx - 33 * i; }
    else { int r = idx - 1056; i = 32 + (r >> 5); t = r & 31; }
}

// ======= kernel A: fused normalize -> e4m3 + exact pos sims + zero ======
__global__ void k_norm_pos(const float* __restrict__ f1, const float* __restrict__ f2,
                           float* __restrict__ out) {
    int i = blockIdx.x;   // 0..4095
    int tid = threadIdx.x;  // 128
    if (tid == 0) { g_rowsum[i] = 0.f; g_rowsum[i + NB] = 0.f; }
    if (i == 0 && tid == 1) out[0] = 0.f;
    float4 v1 = *reinterpret_cast<const float4*>(f1 + (size_t)i * NDIM + tid * 4);
    float4 v2 = *reinterpret_cast<const float4*>(f2 + (size_t)i * NDIM + tid * 4);
    float s11 = v1.x * v1.x + v1.y * v1.y + v1.z * v1.z + v1.w * v1.w;
    float s22 = v2.x * v2.x + v2.y * v2.y + v2.z * v2.z + v2.w * v2.w;
    float s12 = v1.x * v2.x + v1.y * v2.y + v1.z * v2.z + v1.w * v2.w;
#pragma unroll
    for (int o = 16; o > 0; o >>= 1) {
        s11 += __shfl_xor_sync(0xFFFFFFFFu, s11, o);
        s22 += __shfl_xor_sync(0xFFFFFFFFu, s22, o);
        s12 += __shfl_xor_sync(0xFFFFFFFFu, s12, o);
    }
    __shared__ float r11[4], r22[4], r12[4];
    if ((tid & 31) == 0) { r11[tid >> 5] = s11; r22[tid >> 5] = s22; r12[tid >> 5] = s12; }
    __syncthreads();
    float t11 = r11[0] + r11[1] + r11[2] + r11[3];
    float t22 = r22[0] + r22[1] + r22[2] + r22[3];
    float inv1 = 1.f / fmaxf(sqrtf(t11), 1e-12f);
    float inv2 = 1.f / fmaxf(sqrtf(t22), 1e-12f);
    float sc1 = 16.f * inv1, sc2 = 16.f * inv2;
    reinterpret_cast<uint32_t*>(g_F8)[(size_t)i * (NDIM / 4) + tid] =
        pack_e4m3x4(v1.x * sc1, v1.y * sc1, v1.z * sc1, v1.w * sc1);
    reinterpret_cast<uint32_t*>(g_F8)[(size_t)(i + NB) * (NDIM / 4) + tid] =
        pack_e4m3x4(v2.x * sc2, v2.y * sc2, v2.z * sc2, v2.w * sc2);
    if (tid == 0) {
        float t12 = r12[0] + r12[1] + r12[2] + r12[3];
        g_pos[i] = t12 * inv1 * inv2 * 10.f;
    }
}

// ======================= kernel C: symmetric fused GEMM + exp-sum
// FP8, 256 threads = 8 warps (4M x 2N), warp tile 32x64, 296 CTAs,
// 2 CTAs/SM (112 KB smem, <=128 regs). SMEM: A 128x512 e4m3 pitch 512B
// swizzled (64 KB); B 3-ring of 128x128 fp8-k chunks pitch 128B (48 KB).
// 4 chunks per tile, prefetch distance 2, single-buffered fragments
// (cross-CTA overlap hides ldsm latency and barrier/epilogue bubbles).
static constexpr int A_PITCH_B = 512;
static constexpr int B_PITCH_B = 128;
static constexpr int A_BYTES = 128 * A_PITCH_B;             // 65536
static constexpr int B_BUF_BYTES = 128 * B_PITCH_B;         // 16384
static constexpr int SMEM_DYN = A_BYTES + 3 * B_BUF_BYTES;  // 114688

__device__ __forceinline__ uint32_t swz(uint32_t row, uint32_t byteoff) {
    return byteoff ^ ((row & 7) << 4);
}

__device__ __forceinline__ void issue_chunk(uint32_t B_base, int tid, int i, int t0, int c) {
    int t = t0 + (c >> 2);
    int n0 = ((i + t) & 63) * 128;
    int kc = c & 3;  // 128 fp8-k per chunk
    uint32_t buf = B_base + (uint32_t)(c % 3) * B_BUF_BYTES;
#pragma unroll
    for (int u = 0; u < 4; u++) {
        int x = tid + u * NTHREADS;
        uint32_t row = (uint32_t)x >> 3, g = (uint32_t)x & 7;
        cp16(buf + row * B_PITCH_B + swz(row, g * 16),
             &g_F8[(size_t)(n0 + (int)row) * NDIM + kc * 128 + (int)g * 16]);
    }
}

__global__ __launch_bounds__(NTHREADS, 2) void k_infonce() {
    extern __shared__ char dyn[];
    uint32_t A_base = smem_u32(dyn);
    uint32_t B_base = A_base + A_BYTES;
    __shared__ float srow[128];

    int tid = threadIdx.x;
    int wid = tid >> 5, lane = tid & 31;
    int warpm = wid >> 1, warpn = wid & 1;  // 4 x 2, warp tile 32x64
    int g = blockIdx.x;
    int s = (g * NTILES_TOTAL) / NCTA;
    int e = ((g + 1) * NTILES_TOTAL) / NCTA;

    int rowadd = ((lane >> 3) & 1) * 8 + (lane & 7);
    int kadd = (lane >> 4) * 16;
    uint32_t xorm = ((uint32_t)lane & 7) << 4;

    uint32_t aRow[2];
#pragma unroll
    for (int mf = 0; mf < 2; mf++)
        aRow[mf] = A_base + (uint32_t)(warpm * 32 + mf * 16 + rowadd) * A_PITCH_B;
    uint32_t bRowRel[4];
#pragma unroll
    for (int nf = 0; nf < 4; nf++)
        bRowRel[nf] = (uint32_t)(warpn * 64 + nf * 16 + rowadd) * B_PITCH_B;

    float acc[2][8][4];  // [mf][q=nf*2+half][j]
    uint32_t af[2][4], bf[4][4];

    while (s < e) {
        int rowtile, t0;
        decode_tile(s, rowtile, t0);
        int Trow = (rowtile < 32) ? 33 : 32;
        int ntiles = min(e - s, Trow - t0);
        s += ntiles;
        int C = ntiles * 4;  // 128-k chunks
        int m0 = rowtile * 128;
        int grBase = m0 + warpm * 32 + (lane >> 2);
        float accRow[4] = {0.f, 0.f, 0.f, 0.f};

        if (tid < 128) srow[tid] = 0.f;

        // A via cp.async: 64 KB, 4096 16B-groups, swizzled, pitch 512.
#pragma unroll
        for (int u = 0; u < 16; u++) {
            int x = tid + u * NTHREADS;
            uint32_t row = (uint32_t)x >> 5, gg = (uint32_t)x & 31;
            cp16(A_base + row * A_PITCH_B + swz(row, gg * 16),
                 &g_F8[(size_t)(m0 + (int)row) * NDIM + (int)gg * 16]);
        }
        cp_commit();
        issue_chunk(B_base, tid, rowtile, t0, 0);
        cp_commit();
        issue_chunk(B_base, tid, rowtile, t0, 1);
        cp_commit();

        for (int c = 0; c < C; ++c) {
            cp_wait<1>();     // chunk c (and A) complete; chunk c+1 may pend
            __syncthreads();  // visible to all; buf (c-1)%3 free for c+2
            if (c + 2 < C) issue_chunk(B_base, tid, rowtile, t0, c + 2);
            cp_commit();      // one group per iteration (possibly empty)

            int kc = c & 3;
            int t = t0 + (c >> 2);
            int n0 = ((rowtile + t) & 63) * 128;
            if (kc == 0) {
#pragma unroll
                for (int mf = 0; mf < 2; mf++)
#pragma unroll
                    for (int q = 0; q < 8; q++)
#pragma unroll
                        for (int j = 0; j < 4; j++) acc[mf][q][j] = 0.f;
            }

            uint32_t bBuf = B_base + (uint32_t)(c % 3) * B_BUF_BYTES;
#pragma unroll
            for (int ks = 0; ks < 4; ++ks) {
                uint32_t koffA = (uint32_t)(kc * 128 + ks * 32 + kadd) ^ xorm;
                uint32_t koffB = (uint32_t)(ks * 32 + kadd) ^ xorm;
#pragma unroll
                for (int mf = 0; mf < 2; mf++)
                    ldsm_x4(af[mf][0], af[mf][1], af[mf][2], af[mf][3],
                            aRow[mf] + koffA);
#pragma unroll
                for (int nf = 0; nf < 4; nf++)
                    ldsm_x4(bf[nf][0], bf[nf][1], bf[nf][2], bf[nf][3],
                            bBuf + bRowRel[nf] + koffB);
#pragma unroll
                for (int nf = 0; nf < 4; nf++) {
#pragma unroll
                    for (int mf = 0; mf < 2; mf++) {
                        mma16832(acc[mf][nf * 2 + 0], af[mf][0], af[mf][1],
                                 af[mf][2], af[mf][3], bf[nf][0], bf[nf][2]);
                        mma16832(acc[mf][nf * 2 + 1], af[mf][0], af[mf][1],
                                 af[mf][2], af[mf][3], bf[nf][1], bf[nf][3]);
                    }
                }
            }

            if (kc != 3) continue;

            // ---------------- per-tile epilogue ----------------
            if (t == 0) {
                // Diagonal tile: row sums only, self-similarity masked.
#pragma unroll
                for (int mf = 0; mf < 2; mf++) {
                    int gr0 = grBase + mf * 16;
#pragma unroll
                    for (int q = 0; q < 8; q++) {
                        int c0 = n0 + warpn * 64 + (q >> 1) * 16 + (q & 1) * 8 + 2 * (lane & 3);
#pragma unroll
                        for (int j = 0; j < 4; j++) {
                            float arg = fmaf(acc[mf][q][j], EX2_A, EX2_B);
                            float ev;
                            asm("ex2.approx.ftz.f32 %0, %1;" : "=f"(ev) : "f"(arg));
                            int gc = c0 + (j & 1);
                            int gr = gr0 + (j >> 1) * 8;
                            if (gc != gr) accRow[mf * 2 + (j >> 1)] += ev;
                        }
                    }
                }
            } else {
                // Off-diagonal tile: rows (tile i) + columns (tile j).
                float colAcc[16];
#pragma unroll
                for (int x = 0; x < 16; x++) colAcc[x] = 0.f;
#pragma unroll
                for (int mf = 0; mf < 2; mf++) {
#pragma unroll
                    for (int q = 0; q < 8; q++) {
#pragma unroll
                        for (int j = 0; j < 4; j++) {
                            float arg = fmaf(acc[mf][q][j], EX2_A, EX2_B);
                            float ev;
                            asm("ex2.approx.ftz.f32 %0, %1;" : "=f"(ev) : "f"(arg));
                            accRow[mf * 2 + (j >> 1)] += ev;
                            colAcc[q * 2 + (j & 1)] += ev;
                        }
                    }
                }
#pragma unroll
                for (int x = 0; x < 16; x++) {
                    float v = colAcc[x];
                    v += __shfl_xor_sync(0xFFFFFFFFu, v, 4);
                    v += __shfl_xor_sync(0xFFFFFFFFu, v, 8);
                    v += __shfl_xor_sync(0xFFFFFFFFu, v, 16);
                    if (lane < 4) {
                        int q = x >> 1, jlo = x & 1;
                        int col = n0 + warpn * 64 + (q >> 1) * 16 + (q & 1) * 8 + 2 * lane + jlo;
                        atomicAdd(&g_rowsum[col], v);
                    }
                }
            }
        }

        // Segment row flush (also the drain barrier before next A reload).
        __syncthreads();
#pragma unroll
        for (int x = 0; x < 4; x++) {
            float v = accRow[x];
            v += __shfl_xor_sync(0xFFFFFFFFu, v, 1);
            v += __shfl_xor_sync(0xFFFFFFFFu, v, 2);
            if ((lane & 3) == 0)
                atomicAdd(&srow[warpm * 32 + x * 8 + (lane >> 2)], v);
        }
        __syncthreads();
        if (tid < 128)
            atomicAdd(&g_rowsum[m0 + tid], srow[tid]);
    }
}

// ======================= kernel D: final reduction ===============
__global__ void k_finish(float* __restrict__ out) {
    int tid = threadIdx.x;  // 256, grid 32
    int r = blockIdx.x * 256 + tid;
    float acc = 10.f + __logf(g_rowsum[r]) - g_pos[r & (NB - 1)];
#pragma unroll
    for (int o = 16; o > 0; o >>= 1) acc += __shfl_xor_sync(0xFFFFFFFFu, acc, o);
    __shared__ float sred[8];
    if ((tid & 31) == 0) sred[tid >> 5] = acc;
    __syncthreads();
    if (tid == 0) {
        float ssum = 0.f;
#pragma unroll
        for (int i = 0; i < 8; i++) ssum += sred[i];
        atomicAdd(out, ssum * (1.f / (float)NROWS));
    }
}

// ======================= launch ==================================
extern "C" void kernel_launch(void* const* d_in, const int* in_sizes, int n_in,
                              void* d_out, int out_size) {
    const float* f1 = (const float*)d_in[0];
    const float* f2 = (const float*)d_in[1];
    float* out = (float*)d_out;

    cudaFuncSetAttribute(k_infonce, cudaFuncAttributeMaxDynamicSharedMemorySize, SMEM_DYN);

    k_norm_pos<<<NB, 128>>>(f1, f2, out);
    k_infonce<<<NCTA, NTHREADS, SMEM_DYN>>>();
    k_finish<<<32, 256>>>(out);
}